// round 17
// baseline (speedup 1.0000x reference)
#include <cuda_runtime.h>
#include <cuda_bf16.h>
#include <cstdint>

#define HH 48
#define WW 160
#define BB 32
#define CIn 32
#define NG 160
#define CO_ 64
#define HOo 24
#define WOo 80
#define CELLSZ 1024
#define DIRSZ (HH*WW*CELLSZ)
#define NPAIR 24

__device__ __nv_bfloat16 g_xhi[HH*WW*BB*CIn];   // [r][c][b][ci]
__device__ __nv_bfloat16 g_xmi[HH*WW*BB*CIn];
__device__ __nv_bfloat16 g_xlo[HH*WW*BB*CIn];
__device__ float    g_hd [4*DIRSZ];             // scan coords, [b*32+ch]
__device__ float    g_cd [4*DIRSZ];             // boundary rows
__device__ unsigned g_prog[4*NPAIR];
__device__ float    g_y [BB*CO_*HOo*WOo];
__device__ float    g_ps1[BB*HOo*CO_];
__device__ float    g_ps2[BB*HOo*CO_];
__device__ float    g_sc[CO_];
__device__ float    g_sh[CO_];

__device__ __forceinline__ unsigned ld_acq(const unsigned* p) {
    unsigned v; asm volatile("ld.acquire.gpu.global.u32 %0, [%1];" : "=r"(v) : "l"(p) : "memory"); return v;
}
__device__ __forceinline__ void st_rel(unsigned* p, unsigned v) {
    asm volatile("st.release.gpu.global.u32 [%0], %1;" :: "l"(p), "r"(v) : "memory");
}
__device__ __forceinline__ float fsigmoid(float x) { float e = __expf(-x); return __fdividef(1.0f, 1.0f + e); }
__device__ __forceinline__ float ftanh(float x) {
    float ax = fabsf(x); float e = __expf(-2.0f*ax);
    return copysignf(__fdividef(1.0f - e, 1.0f + e), x);
}
__device__ __forceinline__ void split3(float v, unsigned short& h, unsigned short& m, unsigned short& l) {
    __nv_bfloat16 b0 = __float2bfloat16(v);
    float r1 = v - __bfloat162float(b0);
    __nv_bfloat16 b1 = __float2bfloat16(r1);
    __nv_bfloat16 b2 = __float2bfloat16(r1 - __bfloat162float(b1));
    h = __bfloat16_as_ushort(b0); m = __bfloat16_as_ushort(b1); l = __bfloat16_as_ushort(b2);
}
__device__ __forceinline__ uint32_t smem_u32(const void* p) {
    uint32_t a; asm("{ .reg .u64 t; cvta.to.shared.u64 t, %1; cvt.u32.u64 %0, t; }" : "=r"(a) : "l"(p)); return a;
}
#define LDSM4(r, addr) \
    asm volatile("ldmatrix.sync.aligned.m8n8.x4.shared.b16 {%0,%1,%2,%3}, [%4];" \
        : "=r"((r)[0]), "=r"((r)[1]), "=r"((r)[2]), "=r"((r)[3]) : "r"(addr))
#define MMA(d, a, b0, b1) \
    asm volatile("mma.sync.aligned.m16n8k16.row.col.f32.bf16.bf16.f32 " \
        "{%0,%1,%2,%3}, {%4,%5,%6,%7}, {%8,%9}, {%0,%1,%2,%3};" \
        : "+f"((d)[0]), "+f"((d)[1]), "+f"((d)[2]), "+f"((d)[3]) \
        : "r"((a)[0]), "r"((a)[1]), "r"((a)[2]), "r"((a)[3]), "r"(b0), "r"(b1))

__global__ void prep_kernel(const float* __restrict__ x) {
    int t = blockIdx.x * blockDim.x + threadIdx.x;
    if (t < 4*NPAIR) g_prog[t] = 0;
    int i0 = t*4;
    int ci = i0 & 31, b = (i0>>5) & 31, c = (i0>>10) % WW, r = i0/(WW*CELLSZ);
    const float* xp = x + (((size_t)(b*CIn + ci))*HH + r)*WW + c;
    const size_t s = (size_t)HH*WW;
    unsigned short h[4], m[4], l[4];
    #pragma unroll
    for (int j = 0; j < 4; ++j) split3(xp[j*s], h[j], m[j], l[j]);
    *(uint2*)(g_xhi + i0) = make_uint2((unsigned)h[0]|((unsigned)h[1]<<16), (unsigned)h[2]|((unsigned)h[3]<<16));
    *(uint2*)(g_xmi + i0) = make_uint2((unsigned)m[0]|((unsigned)m[1]<<16), (unsigned)m[2]|((unsigned)m[3]<<16));
    *(uint2*)(g_xlo + i0) = make_uint2((unsigned)l[0]|((unsigned)l[1]<<16), (unsigned)l[2]|((unsigned)l[3]<<16));
}
__global__ void noop_kernel() {}

// ---------------- MDLSTM: 96 CTAs x 512 thr, HMMA, 3-way split, split-k ----------------
// LDA=208 (16B multiple -> ldmatrix-legal). Ct1 eliminated via register c-carry.
#define LDA 208          // bytes per A/W row (104 bf16)
#define ZP  160          // Zs pitch (floats)
#define SM_AH 0
#define SM_AM 13312
#define SM_AL 26624
#define SM_WH 39936
#define SM_WM 73216
#define SM_WL 106496
#define SM_ZS 139776
#define SM_Z2 180736
#define SM_CT0 221696
#define SM_TOTB 225792

__launch_bounds__(512)
__global__ void mdlstm_kernel(const float* __restrict__ Wx, const float* __restrict__ Ul,
                              const float* __restrict__ Ut, const float* __restrict__ bias) {
    extern __shared__ char smc[];
    float* Zs  = (float*)(smc + SM_ZS);
    float* Zs2 = (float*)(smc + SM_Z2);
    float* Ct0 = (float*)(smc + SM_CT0);

    const int tid = threadIdx.x, w = tid >> 5, l = tid & 31;
    const int d = blockIdx.x / NPAIR, p = blockIdx.x % NPAIR;
    const bool flipH = (d >= 2), flipW = (d & 1);
    const int r0 = 2*p, r1 = 2*p + 1;
    const int r0o = flipH ? (HH-1-r0) : r0;
    const int r1o = flipH ? (HH-1-r1) : r1;

    // zero A tiles (3 x 13312 B) + Ct0
    for (int i = tid; i < 9984; i += 512) ((unsigned*)smc)[i] = 0u;
    for (int i = tid; i < 1024; i += 512) Ct0[i] = 0.0f;
    // stage W 3-way split: [n][k], pitch 104 bf16
    for (int idx = tid; idx < NG*96; idx += 512) {
        int n = idx/96, k = idx%96;
        float wv = (k < 32) ? Wx[(d*32+k)*NG + n] : (k < 64) ? Ul[(d*32+k-32)*NG + n]
                 : Ut[(d*32+k-64)*NG + n];
        unsigned short h, m, lo; split3(wv, h, m, lo);
        *(unsigned short*)(smc + SM_WH + n*LDA + k*2) = h;
        *(unsigned short*)(smc + SM_WM + n*LDA + k*2) = m;
        *(unsigned short*)(smc + SM_WL + n*LDA + k*2) = lo;
    }
    __syncthreads();

    // GEMM map: kh = w>>3 (k half), rowg = (w&3)*16, nbase = ((w>>2)&1)*80
    const int kh    = w >> 3;
    const int rowg  = (w & 3) * 16;
    const int nbase = ((w >> 2) & 1) * 80;
    float breg[10][2];
    #pragma unroll
    for (int nt = 0; nt < 10; ++nt) {
        breg[nt][0] = (kh == 0) ? bias[d*NG + nbase + nt*8 + (l&3)*2]     : 0.0f;
        breg[nt][1] = (kh == 0) ? bias[d*NG + nbase + nt*8 + (l&3)*2 + 1] : 0.0f;
    }
    const uint32_t smb = smem_u32(smc);
    const uint32_t aAH = smb + SM_AH + (rowg + (l&15))*LDA + kh*96 + (l>>4)*16;
    const uint32_t aAM = aAH + (SM_AM - SM_AH);
    const uint32_t aAL = aAH + (SM_AL - SM_AH);
    const uint32_t bBH = smb + SM_WH + (nbase + (l&15))*LDA + kh*96 + (l>>4)*16;
    const uint32_t bBM = bBH + (SM_WM - SM_WH);
    const uint32_t bBL = bBH + (SM_WL - SM_WH);
    float* Zmy = (kh == 0) ? Zs : Zs2;

    // gates map: thread owns (b, ch0..ch0+1) for BOTH cells (register c-carry)
    const int gbt  = tid >> 4;           // b 0..31
    const int gch0 = (tid & 15) * 2;     // 0,2,...,30
    // staging map: srow = tid>>3 (0..63), 4 ci each
    const int srow = tid >> 3, sci = (tid & 7) * 4;
    unsigned* myflag = &g_prog[d*NPAIR + p];
    const unsigned* upflag = (p > 0) ? &g_prog[d*NPAIR + p - 1] : 0;
    float creg0[2] = {0.0f, 0.0f};   // c(r0, prev col) -> also c_top for cell1
    float creg1[2] = {0.0f, 0.0f};   // c(r1, prev col)

    for (int t = 0; t <= WW; ++t) {
        // ---------- staging ----------
        {
            int cr = srow >> 5, brow = srow & 31;
            bool act = cr ? (t >= 1) : (t < WW);
            uint2 xh, xm, xl;
            if (act) {
                int cc = cr ? t-1 : t;
                int c = flipW ? (WW-1-cc) : cc;
                size_t base = (((size_t)((cr ? r1o : r0o)*WW + c))*32 + brow)*32 + sci;
                xh = *(const uint2*)(g_xhi + base);
                xm = *(const uint2*)(g_xmi + base);
                xl = *(const uint2*)(g_xlo + base);
            }
            if (t < WW && p > 0) {
                if (tid == 0) { while ((int)ld_acq(upflag) < t + 1) { } }
                __syncthreads();
                size_t hb = (((size_t)(d*HH + r0 - 1))*WW + t)*CELLSZ;
                if (tid < 256) {
                    int sb = tid >> 3, g4 = (tid & 7)*4;
                    const float* hp = g_hd + hb + sb*32 + g4;
                    unsigned short sh[4], sm[4], sl[4];
                    #pragma unroll
                    for (int j = 0; j < 4; ++j) split3(hp[j], sh[j], sm[j], sl[j]);
                    *(uint2*)(smc + SM_AH + sb*LDA + (64+g4)*2) =
                        make_uint2((unsigned)sh[0]|((unsigned)sh[1]<<16), (unsigned)sh[2]|((unsigned)sh[3]<<16));
                    *(uint2*)(smc + SM_AM + sb*LDA + (64+g4)*2) =
                        make_uint2((unsigned)sm[0]|((unsigned)sm[1]<<16), (unsigned)sm[2]|((unsigned)sm[3]<<16));
                    *(uint2*)(smc + SM_AL + sb*LDA + (64+g4)*2) =
                        make_uint2((unsigned)sl[0]|((unsigned)sl[1]<<16), (unsigned)sl[2]|((unsigned)sl[3]<<16));
                } else {
                    int v = tid - 256;
                    int sb = v >> 3, g4 = (v & 7)*4;
                    *(float4*)(Ct0 + sb*32 + g4) = *(const float4*)(g_cd + hb + sb*32 + g4);
                }
            }
            if (act) {
                *(uint2*)(smc + SM_AH + srow*LDA + sci*2) = xh;
                *(uint2*)(smc + SM_AM + srow*LDA + sci*2) = xm;
                *(uint2*)(smc + SM_AL + srow*LDA + sci*2) = xl;
            }
        }
        __syncthreads();

        // ---------- GEMM: 6-term 3-way bf16 split, split-k across warp-groups ----------
        {
            float acc[10][4];
            #pragma unroll
            for (int nt = 0; nt < 10; ++nt) {
                acc[nt][0] = breg[nt][0]; acc[nt][2] = breg[nt][0];
                acc[nt][1] = breg[nt][1]; acc[nt][3] = breg[nt][1];
            }
            #pragma unroll
            for (int kt = 0; kt < 3; ++kt) {
                uint32_t ah[4], am[4], al[4];
                LDSM4(ah, aAH + kt*32);
                LDSM4(am, aAM + kt*32);
                LDSM4(al, aAL + kt*32);
                #pragma unroll
                for (int np = 0; np < 5; ++np) {
                    uint32_t bh[4], bm[4], bl[4];
                    LDSM4(bh, bBH + np*(16*LDA) + kt*32);
                    LDSM4(bm, bBM + np*(16*LDA) + kt*32);
                    LDSM4(bl, bBL + np*(16*LDA) + kt*32);
                    MMA(acc[2*np],   ah, bh[0], bh[2]);
                    MMA(acc[2*np],   ah, bm[0], bm[2]);
                    MMA(acc[2*np],   am, bh[0], bh[2]);
                    MMA(acc[2*np],   ah, bl[0], bl[2]);
                    MMA(acc[2*np],   am, bm[0], bm[2]);
                    MMA(acc[2*np],   al, bh[0], bh[2]);
                    MMA(acc[2*np+1], ah, bh[1], bh[3]);
                    MMA(acc[2*np+1], ah, bm[1], bm[3]);
                    MMA(acc[2*np+1], am, bh[1], bh[3]);
                    MMA(acc[2*np+1], ah, bl[1], bl[3]);
                    MMA(acc[2*np+1], am, bm[1], bm[3]);
                    MMA(acc[2*np+1], al, bh[1], bh[3]);
                }
            }
            int rbase = rowg + (l >> 2);
            int cb = nbase + (l & 3)*2;
            #pragma unroll
            for (int nt = 0; nt < 10; ++nt) {
                *(float2*)(Zmy + rbase*ZP + cb + nt*8)     = make_float2(acc[nt][0], acc[nt][1]);
                *(float2*)(Zmy + (rbase+8)*ZP + cb + nt*8) = make_float2(acc[nt][2], acc[nt][3]);
            }
        }
        __syncthreads();

        // ---------- gates: thread owns (gbt, gch0..gch0+1), BOTH cells ----------
        {
            // cell1 FIRST: c_top = creg0 (this thread's c(r0, t-1))
            if (t >= 1) {
                size_t gb1 = (((size_t)(d*HH + r1))*WW + (t-1))*CELLSZ;
                const float* z1 = Zs  + (32 + gbt)*ZP;
                const float* z2 = Zs2 + (32 + gbt)*ZP;
                float hv[2];
                unsigned short s3[3][2];
                #pragma unroll
                for (int j = 0; j < 2; ++j) {
                    int ch = gch0 + j;
                    float zi  = z1[ch]     + z2[ch];
                    float zfl = z1[32+ch]  + z2[32+ch];
                    float zft = z1[64+ch]  + z2[64+ch];
                    float zo  = z1[96+ch]  + z2[96+ch];
                    float zg  = z1[128+ch] + z2[128+ch];
                    float cs = fsigmoid(zfl)*creg1[j] + fsigmoid(zft)*creg0[j]
                             + fsigmoid(zi)*ftanh(zg);
                    float hh = fsigmoid(zo)*ftanh(cs);
                    creg1[j] = cs; hv[j] = hh;
                    split3(hh, s3[0][j], s3[1][j], s3[2][j]);
                }
                *(unsigned*)(smc + SM_AH + (32+gbt)*LDA + (32+gch0)*2) =
                    (unsigned)s3[0][0] | ((unsigned)s3[0][1] << 16);
                *(unsigned*)(smc + SM_AM + (32+gbt)*LDA + (32+gch0)*2) =
                    (unsigned)s3[1][0] | ((unsigned)s3[1][1] << 16);
                *(unsigned*)(smc + SM_AL + (32+gbt)*LDA + (32+gch0)*2) =
                    (unsigned)s3[2][0] | ((unsigned)s3[2][1] << 16);
                *(float2*)(g_hd + gb1 + gbt*32 + gch0) = make_float2(hv[0], hv[1]);
                *(float2*)(g_cd + gb1 + gbt*32 + gch0) = make_float2(creg1[0], creg1[1]);
            }
            // cell0: updates creg0
            if (t < WW) {
                size_t gb0 = (((size_t)(d*HH + r0))*WW + t)*CELLSZ;
                const float* z1 = Zs  + gbt*ZP;
                const float* z2 = Zs2 + gbt*ZP;
                float hv[2];
                unsigned short s3[3][2];
                #pragma unroll
                for (int j = 0; j < 2; ++j) {
                    int ch = gch0 + j;
                    float zi  = z1[ch]     + z2[ch];
                    float zfl = z1[32+ch]  + z2[32+ch];
                    float zft = z1[64+ch]  + z2[64+ch];
                    float zo  = z1[96+ch]  + z2[96+ch];
                    float zg  = z1[128+ch] + z2[128+ch];
                    float cs = fsigmoid(zfl)*creg0[j] + fsigmoid(zft)*Ct0[gbt*32+ch]
                             + fsigmoid(zi)*ftanh(zg);
                    float hh = fsigmoid(zo)*ftanh(cs);
                    creg0[j] = cs; hv[j] = hh;
                    split3(hh, s3[0][j], s3[1][j], s3[2][j]);
                }
                unsigned u[3];
                #pragma unroll
                for (int q = 0; q < 3; ++q) u[q] = (unsigned)s3[q][0] | ((unsigned)s3[q][1] << 16);
                *(unsigned*)(smc + SM_AH + gbt*LDA + (32+gch0)*2)      = u[0];  // h_left r0
                *(unsigned*)(smc + SM_AM + gbt*LDA + (32+gch0)*2)      = u[1];
                *(unsigned*)(smc + SM_AL + gbt*LDA + (32+gch0)*2)      = u[2];
                *(unsigned*)(smc + SM_AH + (32+gbt)*LDA + (64+gch0)*2) = u[0];  // h_top r1
                *(unsigned*)(smc + SM_AM + (32+gbt)*LDA + (64+gch0)*2) = u[1];
                *(unsigned*)(smc + SM_AL + (32+gbt)*LDA + (64+gch0)*2) = u[2];
                *(float2*)(g_hd + gb0 + gbt*32 + gch0) = make_float2(hv[0], hv[1]);
            }
        }
        __syncthreads();
        if (tid == 0 && t >= 1) { __threadfence(); st_rel(myflag, (unsigned)t); }
    }
}

__launch_bounds__(256, 2)
__global__ void conv_kernel(const float* __restrict__ conv_w, const float* __restrict__ conv_b) {
    extern __shared__ float sm2[];
    float* Hs = sm2;
    float* Wt = sm2 + 10240;
    const int ho = blockIdx.x, b = blockIdx.y, tid = threadIdx.x;
    for (int i = tid; i < 128*64; i += 256) { int co = i & 63, q = i >> 6; Wt[i] = conv_w[co*128 + q]; }
    for (int idx = tid; idx < 2*WW*32; idx += 256) {
        int cl = idx & 31, c = (idx >> 5) % WW, rr = idx/(WW*32), rg = 2*ho + rr;
        float v = 0.0f;
        #pragma unroll
        for (int d = 0; d < 4; ++d) {
            int Rd = (d >= 2) ? (HH-1-rg) : rg;
            int Cd = (d & 1) ? (WW-1-c) : c;
            v += g_hd[(((size_t)(d*HH + Rd))*WW + Cd)*CELLSZ + b*32 + cl];
        }
        Hs[idx] = v;
    }
    __syncthreads();
    const int co = tid >> 2, ws = tid & 3;
    float acc[20];
    #pragma unroll
    for (int j = 0; j < 20; ++j) acc[j] = 0.0f;
    for (int cl = 0; cl < 32; ++cl) {
        float w00 = Wt[(cl*4+0)*64+co], w01 = Wt[(cl*4+1)*64+co];
        float w10 = Wt[(cl*4+2)*64+co], w11 = Wt[(cl*4+3)*64+co];
        #pragma unroll
        for (int j = 0; j < 20; ++j) {
            int c0 = 2*(j*4 + ws);
            acc[j] += Hs[c0*32+cl]*w00 + Hs[(c0+1)*32+cl]*w01 + Hs[(WW+c0)*32+cl]*w10 + Hs[(WW+c0+1)*32+cl]*w11;
        }
    }
    float bb = 4.0f*conv_b[co], s1 = 0.0f, s2 = 0.0f;
    float* ybase = g_y + (((size_t)b*CO_ + co)*HOo + ho)*WOo;
    #pragma unroll
    for (int j = 0; j < 20; ++j) {
        float y = ftanh(acc[j] + bb);
        ybase[j*4 + ws] = y; s1 += y; s2 += y*y;
    }
    s1 += __shfl_down_sync(0xffffffffu, s1, 1, 4); s1 += __shfl_down_sync(0xffffffffu, s1, 2, 4);
    s2 += __shfl_down_sync(0xffffffffu, s2, 1, 4); s2 += __shfl_down_sync(0xffffffffu, s2, 2, 4);
    if (ws == 0) { int pp = b*HOo + ho; g_ps1[pp*CO_ + co] = s1; g_ps2[pp*CO_ + co] = s2; }
}

__global__ void reduce_kernel(const float* __restrict__ gamma, const float* __restrict__ beta) {
    __shared__ float sh1[256], sh2[256];
    const int co = blockIdx.x, t = threadIdx.x;
    float s1 = 0.0f, s2 = 0.0f;
    for (int p = t; p < BB*HOo; p += 256) { s1 += g_ps1[p*CO_ + co]; s2 += g_ps2[p*CO_ + co]; }
    sh1[t] = s1; sh2[t] = s2;
    __syncthreads();
    for (int s = 128; s > 0; s >>= 1) {
        if (t < s) { sh1[t] += sh1[t+s]; sh2[t] += sh2[t+s]; }
        __syncthreads();
    }
    if (t == 0) {
        const float N = (float)(BB*HOo*WOo);
        float mean = sh1[0]/N, var = sh2[0]/N - mean*mean;
        float sc = gamma[co]*rsqrtf(var + 1e-5f);
        g_sc[co] = sc; g_sh[co] = beta[co] - mean*sc;
    }
}

__global__ void norm_kernel(float* __restrict__ out) {
    int t = blockIdx.x*blockDim.x + threadIdx.x;
    int i0 = t*4, co = (i0/(HOo*WOo)) & 63;
    float sc = g_sc[co], sh = g_sh[co];
    float4 v = *(const float4*)(g_y + i0);
    v.x = v.x*sc + sh; v.y = v.y*sc + sh; v.z = v.z*sc + sh; v.w = v.w*sc + sh;
    *(float4*)(out + i0) = v;
}

extern "C" void kernel_launch(void* const* d_in, const int* in_sizes, int n_in,
                              void* d_out, int out_size) {
    (void)in_sizes; (void)n_in; (void)out_size;
    const float* x      = (const float*)d_in[0];
    const float* Wx     = (const float*)d_in[1];
    const float* Ul     = (const float*)d_in[2];
    const float* Ut     = (const float*)d_in[3];
    const float* bias   = (const float*)d_in[4];
    const float* conv_w = (const float*)d_in[5];
    const float* conv_b = (const float*)d_in[6];
    const float* gamma  = (const float*)d_in[7];
    const float* beta   = (const float*)d_in[8];
    float* out = (float*)d_out;

    cudaFuncSetAttribute(mdlstm_kernel, cudaFuncAttributeMaxDynamicSharedMemorySize, SM_TOTB);
    cudaFuncSetAttribute(conv_kernel,   cudaFuncAttributeMaxDynamicSharedMemorySize, (10240+8192)*4);

    prep_kernel<<<7680, 256>>>(x);
    noop_kernel<<<1, 32>>>();
    noop_kernel<<<1, 32>>>();
    mdlstm_kernel<<<4*NPAIR, 512, SM_TOTB>>>(Wx, Ul, Ut, bias);
    conv_kernel<<<dim3(HOo, BB), 256, (10240+8192)*4>>>(conv_w, conv_b);
    reduce_kernel<<<CO_, 256>>>(gamma, beta);
    norm_kernel<<<3840, 256>>>(out);
}